// round 1
// baseline (speedup 1.0000x reference)
#include <cuda_runtime.h>
#include <math.h>

// Problem constants
#define NTOK   16384      // B*S
#define HID    1024
#define G      2
#define V      320
#define GV     640
#define DHALF  128        // CODEVECTOR_DIM / G
#define NBLK_B 256        // blocks per group in row-reduce kernel
#define ROWS_PER_BLK 64   // NTOK / NBLK_B

// Scratch (static device globals — no allocation in kernel_launch)
__device__ float g_logits[(size_t)NTOK * GV];          // 40 MB
__device__ float g_part[G * NBLK_B * V];               // block partial marginals

// ---------------------------------------------------------------------------
// Kernel 1: fp32 SGEMM  logits[m, v] = sum_k hidden[m,k] * W[v,k] + b[v]
// M=16384, N=640, K=1024. NT layout (both operands K-contiguous).
// 128x128 tile, BK=16, 256 threads, 8x8 per-thread microtile.
// ---------------------------------------------------------------------------
#define BM 128
#define BN 128
#define BK 16
#define SPAD 4   // keep float4 alignment of smem rows

__global__ __launch_bounds__(256, 2)
void gemm_kernel(const float* __restrict__ A, const float* __restrict__ Wt,
                 const float* __restrict__ bias) {
    __shared__ float As[BK][BM + SPAD];
    __shared__ float Bs[BK][BN + SPAD];
    const int tid  = threadIdx.x;
    const int m0   = blockIdx.y * BM;
    const int n0   = blockIdx.x * BN;
    const int lrow = tid >> 2;           // 0..63
    const int lkq  = (tid & 3) << 2;     // 0,4,8,12
    const int tr   = tid >> 4;           // 0..15
    const int tc   = tid & 15;           // 0..15

    float acc[8][8];
#pragma unroll
    for (int i = 0; i < 8; i++)
#pragma unroll
        for (int j = 0; j < 8; j++) acc[i][j] = 0.f;

    const float* Ap = A  + (size_t)m0 * HID;
    const float* Wp = Wt + (size_t)n0 * HID;

    for (int k0 = 0; k0 < HID; k0 += BK) {
#pragma unroll
        for (int rr = 0; rr < 2; rr++) {
            const int row = lrow + rr * 64;
            float4 va = *(const float4*)(Ap + (size_t)row * HID + k0 + lkq);
            As[lkq + 0][row] = va.x;
            As[lkq + 1][row] = va.y;
            As[lkq + 2][row] = va.z;
            As[lkq + 3][row] = va.w;
            float4 vb = *(const float4*)(Wp + (size_t)row * HID + k0 + lkq);
            Bs[lkq + 0][row] = vb.x;
            Bs[lkq + 1][row] = vb.y;
            Bs[lkq + 2][row] = vb.z;
            Bs[lkq + 3][row] = vb.w;
        }
        __syncthreads();
#pragma unroll
        for (int k = 0; k < BK; k++) {
            float a[8], bv[8];
            *(float4*)&a[0]  = *(const float4*)&As[k][tr * 8];
            *(float4*)&a[4]  = *(const float4*)&As[k][tr * 8 + 4];
            *(float4*)&bv[0] = *(const float4*)&Bs[k][tc * 8];
            *(float4*)&bv[4] = *(const float4*)&Bs[k][tc * 8 + 4];
#pragma unroll
            for (int i = 0; i < 8; i++)
#pragma unroll
                for (int j = 0; j < 8; j++)
                    acc[i][j] = fmaf(a[i], bv[j], acc[i][j]);
        }
        __syncthreads();
    }

    // Epilogue: add bias, store float4 pairs
    const int nb = n0 + tc * 8;
    float4 b0 = *(const float4*)(bias + nb);
    float4 b1 = *(const float4*)(bias + nb + 4);
#pragma unroll
    for (int i = 0; i < 8; i++) {
        const int m = m0 + tr * 8 + i;
        float* dst = g_logits + (size_t)m * GV + nb;
        float4 o0 = make_float4(acc[i][0] + b0.x, acc[i][1] + b0.y,
                                acc[i][2] + b0.z, acc[i][3] + b0.w);
        float4 o1 = make_float4(acc[i][4] + b1.x, acc[i][5] + b1.y,
                                acc[i][6] + b1.z, acc[i][7] + b1.w);
        *(float4*)dst       = o0;
        *(float4*)(dst + 4) = o1;
    }
}

// ---------------------------------------------------------------------------
// Kernel 2: per-(n,g) row: gumbel argmax -> codevector gather (output),
// plus softmax (no gumbel) prob accumulation for the marginal.
// One warp per row; 8 warps per block; 64 rows per block.
// Deterministic: fixed serial accumulation order, no float atomics.
// ---------------------------------------------------------------------------
__global__ __launch_bounds__(256)
void rowreduce_kernel(const float* __restrict__ gumbel_u,
                      const float* __restrict__ codevec,
                      float* __restrict__ out) {
    const int g    = blockIdx.y;
    const int warp = threadIdx.x >> 5;
    const int lane = threadIdx.x & 31;
    __shared__ float marg[8][V];   // per-warp accumulators (lane-private slots)

    for (int v = lane; v < V; v += 32) marg[warp][v] = 0.f;

    const int nbase = blockIdx.x * ROWS_PER_BLK;
    for (int it = 0; it < ROWS_PER_BLK / 8; it++) {
        const int n = nbase + it * 8 + warp;
        const float* lrow = g_logits + (size_t)n * GV + g * V;
        const float* urow = gumbel_u + ((size_t)n * G + g) * V;

        float l[10];
        float key_max = -INFINITY; int key_idx = 0;
        float l_max   = -INFINITY;
#pragma unroll
        for (int s = 0; s < 10; s++) {
            const int v = lane + 32 * s;
            l[s] = lrow[v];
            const float u   = urow[v];
            const float gum = -logf(-logf(u));
            const float key = l[s] + gum;
            if (key > key_max) { key_max = key; key_idx = v; }  // first-max kept
            l_max = fmaxf(l_max, l[s]);
        }
        // warp max of l (for softmax stability)
#pragma unroll
        for (int off = 16; off; off >>= 1)
            l_max = fmaxf(l_max, __shfl_xor_sync(0xffffffffu, l_max, off));
        // warp argmax of key; ties -> lower index (jnp.argmax semantics)
#pragma unroll
        for (int off = 16; off; off >>= 1) {
            const float ok = __shfl_xor_sync(0xffffffffu, key_max, off);
            const int   oi = __shfl_xor_sync(0xffffffffu, key_idx, off);
            if (ok > key_max || (ok == key_max && oi < key_idx)) {
                key_max = ok; key_idx = oi;
            }
        }
        // softmax probs of raw logits (no gumbel, no tau) for the marginal
        float p[10];
        float sum = 0.f;
#pragma unroll
        for (int s = 0; s < 10; s++) { p[s] = expf(l[s] - l_max); sum += p[s]; }
#pragma unroll
        for (int off = 16; off; off >>= 1)
            sum += __shfl_xor_sync(0xffffffffu, sum, off);
        const float inv = 1.f / sum;
#pragma unroll
        for (int s = 0; s < 10; s++)
            marg[warp][lane + 32 * s] += p[s] * inv;

        // output: gather selected codevector row (128 floats; 4 per lane)
        const float4* src = (const float4*)(codevec + (size_t)(g * V + key_idx) * DHALF);
        float4* dst = (float4*)(out + (size_t)n * (2 * DHALF) + g * DHALF);
        dst[lane] = src[lane];
    }
    __syncthreads();

    // reduce 8 warp accumulators -> block partial (deterministic order)
    for (int v = threadIdx.x; v < V; v += 256) {
        float s = 0.f;
#pragma unroll
        for (int w = 0; w < 8; w++) s += marg[w][v];
        g_part[(g * NBLK_B + blockIdx.x) * V + v] = s;
    }
}

// ---------------------------------------------------------------------------
// Kernel 3: finalize perplexity (single block, deterministic serial sums)
// ---------------------------------------------------------------------------
__global__ void finalize_kernel(float* __restrict__ out, int out_size) {
    __shared__ float terms[GV];
    const int t = threadIdx.x;  // 0..639 ; g = t/V, v = t%V
    const int gg = t / V;
    const int vv = t % V;
    float s = 0.f;
    for (int blk = 0; blk < NBLK_B; blk++)
        s += g_part[(gg * NBLK_B + blk) * V + vv];
    const float m = s / (float)NTOK;
    terms[t] = m * logf(m + 1e-7f);
    __syncthreads();
    if (t == 0) {
        float H0 = 0.f, H1 = 0.f;
        for (int v = 0; v < V; v++) { H0 += terms[v]; H1 += terms[V + v]; }
        const float ppl = expf(-H0) + expf(-H1);
        if (out_size > NTOK * 2 * DHALF) out[(size_t)NTOK * 2 * DHALF] = ppl;
    }
}

// ---------------------------------------------------------------------------
extern "C" void kernel_launch(void* const* d_in, const int* in_sizes, int n_in,
                              void* d_out, int out_size) {
    const float* hidden      = (const float*)d_in[0];
    const float* W           = (const float*)d_in[1];
    const float* b           = (const float*)d_in[2];
    const float* codevectors = (const float*)d_in[3];
    const float* gumbel_u    = (const float*)d_in[4];
    float* out = (float*)d_out;

    dim3 ggrid(GV / BN, NTOK / BM);     // (5, 128) = 640 blocks
    gemm_kernel<<<ggrid, 256>>>(hidden, W, b);

    dim3 bgrid(NBLK_B, G);              // (256, 2)
    rowreduce_kernel<<<bgrid, 256>>>(gumbel_u, codevectors, out);

    finalize_kernel<<<1, GV>>>(out, out_size);
}

// round 6
// speedup vs baseline: 2.3039x; 2.3039x over previous
#include <cuda_runtime.h>
#include <cuda_fp16.h>
#include <math.h>
#include <stdint.h>

// Problem constants
#define NTOK   16384
#define HID    1024
#define G      2
#define V      320
#define GV     640
#define DHALF  128
#define NBLK_B 256
#define ROWS_PER_BLK 64

// GEMM tiling
#define MT    128
#define NTL   64
#define BKH   64                 // halves per K chunk (=128 bytes/row)
#define NCHK  (HID / BKH)        // 16
#define A_SP  (128 * 128)        // bytes per A split tile
#define B_SP  (64 * 128)
#define STG   (2 * A_SP + 2 * B_SP)   // 49152
#define NSTG  3
#define SMEM_GEMM (NSTG * STG)   // 147456

// Scratch (static device globals)
__device__ float  g_logits[(size_t)NTOK * GV];
__device__ float  g_part[G * NBLK_B * V];
__device__ __half g_Ahi[(size_t)NTOK * HID];
__device__ __half g_Alo[(size_t)NTOK * HID];
__device__ __half g_Whi[(size_t)GV * HID];
__device__ __half g_Wlo[(size_t)GV * HID];

// ---------------- PTX helpers (baseline sm_80+ features only) ----------------
__device__ __forceinline__ uint32_t smem_u32(const void* p) {
    uint32_t a;
    asm("{ .reg .u64 t; cvta.to.shared.u64 t, %1; cvt.u32.u64 %0, t; }" : "=r"(a) : "l"(p));
    return a;
}
__device__ __forceinline__ uint32_t sw128(uint32_t x) { return x ^ ((x >> 3) & 0x70); }

#define CPA16(d, s) asm volatile("cp.async.cg.shared.global [%0], [%1], 16;" :: "r"(d), "l"(s))
#define CP_COMMIT() asm volatile("cp.async.commit_group;" ::: "memory")
#define CP_WAIT1()  asm volatile("cp.async.wait_group 1;" ::: "memory")

#define LDSM4(r0, r1, r2, r3, a)                                                   \
    asm volatile("ldmatrix.sync.aligned.m8n8.x4.shared.b16 {%0,%1,%2,%3}, [%4];"   \
                 : "=r"(r0), "=r"(r1), "=r"(r2), "=r"(r3) : "r"(a))

#define MMA16816(d, a, b0v, b1v)                                                   \
    asm volatile("mma.sync.aligned.m16n8k16.row.col.f32.f16.f16.f32 "              \
                 "{%0,%1,%2,%3}, {%4,%5,%6,%7}, {%8,%9}, {%0,%1,%2,%3};"           \
                 : "+f"((d)[0]), "+f"((d)[1]), "+f"((d)[2]), "+f"((d)[3])          \
                 : "r"((a)[0]), "r"((a)[1]), "r"((a)[2]), "r"((a)[3]),             \
                   "r"(b0v), "r"(b1v))

// ---------------------------------------------------------------------------
// Kernel 0: fp32 -> (hi fp16, lo fp16 * 4096) split for A and W
// ---------------------------------------------------------------------------
__global__ __launch_bounds__(256)
void split_kernel(const float* __restrict__ A, const float* __restrict__ W) {
    const size_t totA = (size_t)NTOK * (HID / 4);
    const size_t tot  = totA + (size_t)GV * (HID / 4);
    for (size_t i = (size_t)blockIdx.x * blockDim.x + threadIdx.x; i < tot;
         i += (size_t)gridDim.x * blockDim.x) {
        float4 v;
        uint2 *dh, *dl;
        if (i < totA) {
            v  = ((const float4*)A)[i];
            dh = (uint2*)g_Ahi + i;
            dl = (uint2*)g_Alo + i;
        } else {
            const size_t j = i - totA;
            v  = ((const float4*)W)[j];
            dh = (uint2*)g_Whi + j;
            dl = (uint2*)g_Wlo + j;
        }
        float xs[4] = {v.x, v.y, v.z, v.w};
        uint16_t h[4], l[4];
#pragma unroll
        for (int e = 0; e < 4; e++) {
            __half hh = __float2half_rn(xs[e]);
            h[e] = __half_as_ushort(hh);
            l[e] = __half_as_ushort(__float2half_rn((xs[e] - __half2float(hh)) * 4096.0f));
        }
        uint2 hp, lp;
        hp.x = (uint32_t)h[0] | ((uint32_t)h[1] << 16);
        hp.y = (uint32_t)h[2] | ((uint32_t)h[3] << 16);
        lp.x = (uint32_t)l[0] | ((uint32_t)l[1] << 16);
        lp.y = (uint32_t)l[2] | ((uint32_t)l[3] << 16);
        *dh = hp;
        *dl = lp;
    }
}

// ---------------------------------------------------------------------------
// Kernel 1: fp16-split HMMA GEMM.  logits = A * W^T + b  (M=16384,N=640,K=1024)
// CTA 128x64, BK=64 halves, 3-stage cp.async pipeline, SW128 smem + ldmatrix.
// 8 warps as 4(M) x 2(N); warp tile 32x32; acc0 = hi*hi, acc1 = cross terms.
// ---------------------------------------------------------------------------
__global__ __launch_bounds__(256, 1)
void gemm_hmma(const float* __restrict__ bias) {
    extern __shared__ char smem[];
    const uint32_t sb = smem_u32(smem);
    const int tid  = threadIdx.x;
    const int lane = tid & 31;
    const int wid  = tid >> 5;
    const int wm   = wid >> 1;   // 0..3 -> 32 rows each
    const int wn   = wid & 1;    // 0..1 -> 32 cols each
    const int m0 = blockIdx.y * MT;
    const int n0 = blockIdx.x * NTL;

    // per-lane ldmatrix row-byte offsets (within tile)
    const uint32_t ra = (uint32_t)(wm * 32 + (lane & 15)) * 128;
    const uint32_t ua = (uint32_t)(lane >> 4);            // A unit parity
    const uint32_t rb = (uint32_t)(wn * 32 + (lane & 7) + ((lane >> 4) << 3)) * 128;
    const uint32_t ub = (uint32_t)((lane >> 3) & 1);      // B unit parity

    auto load_stage = [&](int kc, int s) {
        const uint32_t base = sb + s * STG;
        const int k0 = kc * BKH;
#pragma unroll
        for (int i = 0; i < 4; i++) {
            const int q = tid + 256 * i;          // 0..1023
            const int r = q >> 3, u = q & 7;
            const uint32_t off = sw128((uint32_t)(r * 128 + u * 16));
            const size_t gs = (size_t)(m0 + r) * HID + k0 + u * 8;
            CPA16(base + off,        g_Ahi + gs);
            CPA16(base + A_SP + off, g_Alo + gs);
        }
#pragma unroll
        for (int i = 0; i < 2; i++) {
            const int q = tid + 256 * i;          // 0..511
            const int r = q >> 3, u = q & 7;      // r 0..63
            const uint32_t off = sw128((uint32_t)(r * 128 + u * 16));
            const size_t gs = (size_t)(n0 + r) * HID + k0 + u * 8;
            CPA16(base + 2 * A_SP + off,        g_Whi + gs);
            CPA16(base + 2 * A_SP + B_SP + off, g_Wlo + gs);
        }
    };

    float acc0[2][4][4], acc1[2][4][4];
#pragma unroll
    for (int mt = 0; mt < 2; mt++)
#pragma unroll
        for (int nt = 0; nt < 4; nt++)
#pragma unroll
            for (int e = 0; e < 4; e++) { acc0[mt][nt][e] = 0.f; acc1[mt][nt][e] = 0.f; }

    load_stage(0, 0); CP_COMMIT();
    load_stage(1, 1); CP_COMMIT();

    for (int kc = 0; kc < NCHK; kc++) {
        CP_WAIT1();
        __syncthreads();      // stage kc visible; all warps done with stage kc-1
        if (kc + 2 < NCHK) load_stage(kc + 2, (kc + 2) % NSTG);
        CP_COMMIT();

        const uint32_t base = sb + (kc % NSTG) * STG;
        const uint32_t aH = base, aL = base + A_SP;
        const uint32_t bH = base + 2 * A_SP, bL = bH + B_SP;

#pragma unroll
        for (int k16 = 0; k16 < 4; k16++) {
            const uint32_t ucA = (uint32_t)(k16 * 2 + ua) * 16;
            const uint32_t ucB = (uint32_t)(k16 * 2 + ub) * 16;
            uint32_t ah[2][4], al[2][4];
#pragma unroll
            for (int mt = 0; mt < 2; mt++) {
                const uint32_t off = sw128(ra + mt * 2048 + ucA);
                LDSM4(ah[mt][0], ah[mt][1], ah[mt][2], ah[mt][3], aH + off);
                LDSM4(al[mt][0], al[mt][1], al[mt][2], al[mt][3], aL + off);
            }
            uint32_t bh[8], bl[8];
#pragma unroll
            for (int nn = 0; nn < 2; nn++) {
                const uint32_t off = sw128(rb + nn * 2048 + ucB);
                LDSM4(bh[nn * 4 + 0], bh[nn * 4 + 1], bh[nn * 4 + 2], bh[nn * 4 + 3], bH + off);
                LDSM4(bl[nn * 4 + 0], bl[nn * 4 + 1], bl[nn * 4 + 2], bl[nn * 4 + 3], bL + off);
            }
#pragma unroll
            for (int mt = 0; mt < 2; mt++)
#pragma unroll
                for (int nt = 0; nt < 4; nt++) {
                    MMA16816(acc0[mt][nt], ah[mt], bh[nt * 2], bh[nt * 2 + 1]);
                    MMA16816(acc1[mt][nt], ah[mt], bl[nt * 2], bl[nt * 2 + 1]);
                    MMA16816(acc1[mt][nt], al[mt], bh[nt * 2], bh[nt * 2 + 1]);
                }
        }
    }

    // epilogue: logits = acc0 + acc1/4096 + bias
    const int mrow  = m0 + wm * 32 + (lane >> 2);
    const int ncol0 = n0 + wn * 32 + (lane & 3) * 2;
#pragma unroll
    for (int mt = 0; mt < 2; mt++)
#pragma unroll
        for (int nt = 0; nt < 4; nt++) {
            const int r = mrow + mt * 16;
            const int c = ncol0 + nt * 8;
            const float2 bv = *(const float2*)(bias + c);
            float2 o;
            o.x = acc0[mt][nt][0] + acc1[mt][nt][0] * (1.0f / 4096.0f) + bv.x;
            o.y = acc0[mt][nt][1] + acc1[mt][nt][1] * (1.0f / 4096.0f) + bv.y;
            *(float2*)(g_logits + (size_t)r * GV + c) = o;
            o.x = acc0[mt][nt][2] + acc1[mt][nt][2] * (1.0f / 4096.0f) + bv.x;
            o.y = acc0[mt][nt][3] + acc1[mt][nt][3] * (1.0f / 4096.0f) + bv.y;
            *(float2*)(g_logits + (size_t)(r + 8) * GV + c) = o;
        }
}

// ---------------------------------------------------------------------------
// Kernel 2: per-(n,g) row: gumbel argmax -> codevector gather + soft marginal
// ---------------------------------------------------------------------------
__global__ __launch_bounds__(256)
void rowreduce_kernel(const float* __restrict__ gumbel_u,
                      const float* __restrict__ codevec,
                      float* __restrict__ out) {
    const int g    = blockIdx.y;
    const int warp = threadIdx.x >> 5;
    const int lane = threadIdx.x & 31;
    __shared__ float marg[8][V];

    for (int v = lane; v < V; v += 32) marg[warp][v] = 0.f;

    const int nbase = blockIdx.x * ROWS_PER_BLK;
    for (int it = 0; it < ROWS_PER_BLK / 8; it++) {
        const int n = nbase + it * 8 + warp;
        const float* lrow = g_logits + (size_t)n * GV + g * V;
        const float* urow = gumbel_u + ((size_t)n * G + g) * V;

        float l[10];
        float key_max = -INFINITY; int key_idx = 0;
        float l_max   = -INFINITY;
#pragma unroll
        for (int s = 0; s < 10; s++) {
            const int v = lane + 32 * s;
            l[s] = lrow[v];
            const float u   = urow[v];
            const float gum = -logf(-logf(u));
            const float key = l[s] + gum;
            if (key > key_max) { key_max = key; key_idx = v; }
            l_max = fmaxf(l_max, l[s]);
        }
#pragma unroll
        for (int off = 16; off; off >>= 1)
            l_max = fmaxf(l_max, __shfl_xor_sync(0xffffffffu, l_max, off));
#pragma unroll
        for (int off = 16; off; off >>= 1) {
            const float ok = __shfl_xor_sync(0xffffffffu, key_max, off);
            const int   oi = __shfl_xor_sync(0xffffffffu, key_idx, off);
            if (ok > key_max || (ok == key_max && oi < key_idx)) {
                key_max = ok; key_idx = oi;
            }
        }
        float p[10];
        float sum = 0.f;
#pragma unroll
        for (int s = 0; s < 10; s++) { p[s] = expf(l[s] - l_max); sum += p[s]; }
#pragma unroll
        for (int off = 16; off; off >>= 1)
            sum += __shfl_xor_sync(0xffffffffu, sum, off);
        const float inv = 1.f / sum;
#pragma unroll
        for (int s = 0; s < 10; s++)
            marg[warp][lane + 32 * s] += p[s] * inv;

        const float4* src = (const float4*)(codevec + (size_t)(g * V + key_idx) * DHALF);
        float4* dst = (float4*)(out + (size_t)n * (2 * DHALF) + g * DHALF);
        dst[lane] = src[lane];
    }
    __syncthreads();

    for (int v = threadIdx.x; v < V; v += 256) {
        float s = 0.f;
#pragma unroll
        for (int w = 0; w < 8; w++) s += marg[w][v];
        g_part[(g * NBLK_B + blockIdx.x) * V + v] = s;
    }
}

// ---------------------------------------------------------------------------
// Kernel 3: finalize perplexity
// ---------------------------------------------------------------------------
__global__ void finalize_kernel(float* __restrict__ out, int out_size) {
    __shared__ float terms[GV];
    const int t  = threadIdx.x;
    const int gg = t / V;
    const int vv = t % V;
    float s = 0.f;
    for (int blk = 0; blk < NBLK_B; blk++)
        s += g_part[(gg * NBLK_B + blk) * V + vv];
    const float m = s / (float)NTOK;
    terms[t] = m * logf(m + 1e-7f);
    __syncthreads();
    if (t == 0) {
        float H0 = 0.f, H1 = 0.f;
        for (int v = 0; v < V; v++) { H0 += terms[v]; H1 += terms[V + v]; }
        const float ppl = expf(-H0) + expf(-H1);
        if (out_size > NTOK * 2 * DHALF) out[(size_t)NTOK * 2 * DHALF] = ppl;
    }
}

// ---------------------------------------------------------------------------
extern "C" void kernel_launch(void* const* d_in, const int* in_sizes, int n_in,
                              void* d_out, int out_size) {
    const float* hidden      = (const float*)d_in[0];
    const float* W           = (const float*)d_in[1];
    const float* b           = (const float*)d_in[2];
    const float* codevectors = (const float*)d_in[3];
    const float* gumbel_u    = (const float*)d_in[4];
    float* out = (float*)d_out;

    cudaFuncSetAttribute(gemm_hmma, cudaFuncAttributeMaxDynamicSharedMemorySize, SMEM_GEMM);

    split_kernel<<<1024, 256>>>(hidden, W);

    dim3 ggrid(GV / NTL, NTOK / MT);    // (10, 128)
    gemm_hmma<<<ggrid, 256, SMEM_GEMM>>>(b);

    dim3 bgrid(NBLK_B, G);              // (256, 2)
    rowreduce_kernel<<<bgrid, 256>>>(gumbel_u, codevectors, out);

    finalize_kernel<<<1, GV>>>(out, out_size);
}

// round 9
// speedup vs baseline: 2.6357x; 1.1440x over previous
#include <cuda_runtime.h>
#include <cuda_fp16.h>
#include <math.h>
#include <stdint.h>

// Problem constants
#define NTOK   16384
#define HID    1024
#define G      2
#define V      320
#define GV     640
#define DHALF  128
#define NBLK_B 256
#define ROWS_PER_BLK 64

// GEMM tiling
#define MT    128
#define NTL   64
#define BKH   64                 // halves per K chunk (=128 bytes/row)
#define NCHK  (HID / BKH)        // 16
#define A_SP  (128 * 128)        // bytes per A split tile
#define B_SP  (64 * 128)
#define STG   (2 * A_SP + 2 * B_SP)   // 49152
#define NSTG  2
#define SMEM_GEMM (NSTG * STG)   // 98304 -> 2 CTAs/SM

// Scratch (static device globals)
__device__ float  g_logits[(size_t)NTOK * GV];
__device__ float  g_part[G * NBLK_B * V];
__device__ float  g_terms[GV];
__device__ __half g_Ahi[(size_t)NTOK * HID];
__device__ __half g_Alo[(size_t)NTOK * HID];
__device__ __half g_Whi[(size_t)GV * HID];
__device__ __half g_Wlo[(size_t)GV * HID];

// ---------------- PTX helpers (baseline sm_80+ features only) ----------------
__device__ __forceinline__ uint32_t smem_u32(const void* p) {
    uint32_t a;
    asm("{ .reg .u64 t; cvta.to.shared.u64 t, %1; cvt.u32.u64 %0, t; }" : "=r"(a) : "l"(p));
    return a;
}
__device__ __forceinline__ uint32_t sw128(uint32_t x) { return x ^ ((x >> 3) & 0x70); }

#define CPA16(d, s) asm volatile("cp.async.cg.shared.global [%0], [%1], 16;" :: "r"(d), "l"(s))
#define CP_COMMIT() asm volatile("cp.async.commit_group;" ::: "memory")
#define CP_WAIT1()  asm volatile("cp.async.wait_group 1;" ::: "memory")
#define CP_WAIT0()  asm volatile("cp.async.wait_group 0;" ::: "memory")

#define LDSM4(r0, r1, r2, r3, a)                                                   \
    asm volatile("ldmatrix.sync.aligned.m8n8.x4.shared.b16 {%0,%1,%2,%3}, [%4];"   \
                 : "=r"(r0), "=r"(r1), "=r"(r2), "=r"(r3) : "r"(a))

#define MMA16816(d, a, b0v, b1v)                                                   \
    asm volatile("mma.sync.aligned.m16n8k16.row.col.f32.f16.f16.f32 "              \
                 "{%0,%1,%2,%3}, {%4,%5,%6,%7}, {%8,%9}, {%0,%1,%2,%3};"           \
                 : "+f"((d)[0]), "+f"((d)[1]), "+f"((d)[2]), "+f"((d)[3])          \
                 : "r"((a)[0]), "r"((a)[1]), "r"((a)[2]), "r"((a)[3]),             \
                   "r"(b0v), "r"(b1v))

// ---------------------------------------------------------------------------
// Kernel 0: fp32 -> (hi fp16, lo fp16 * 4096) split for A and W
// ---------------------------------------------------------------------------
__global__ __launch_bounds__(256)
void split_kernel(const float* __restrict__ A, const float* __restrict__ W) {
    const size_t totA = (size_t)NTOK * (HID / 4);
    const size_t tot  = totA + (size_t)GV * (HID / 4);
    for (size_t i = (size_t)blockIdx.x * blockDim.x + threadIdx.x; i < tot;
         i += (size_t)gridDim.x * blockDim.x) {
        float4 v;
        uint2 *dh, *dl;
        if (i < totA) {
            v  = ((const float4*)A)[i];
            dh = (uint2*)g_Ahi + i;
            dl = (uint2*)g_Alo + i;
        } else {
            const size_t j = i - totA;
            v  = ((const float4*)W)[j];
            dh = (uint2*)g_Whi + j;
            dl = (uint2*)g_Wlo + j;
        }
        float xs[4] = {v.x, v.y, v.z, v.w};
        uint16_t h[4], l[4];
#pragma unroll
        for (int e = 0; e < 4; e++) {
            __half hh = __float2half_rn(xs[e]);
            h[e] = __half_as_ushort(hh);
            l[e] = __half_as_ushort(__float2half_rn((xs[e] - __half2float(hh)) * 4096.0f));
        }
        uint2 hp, lp;
        hp.x = (uint32_t)h[0] | ((uint32_t)h[1] << 16);
        hp.y = (uint32_t)h[2] | ((uint32_t)h[3] << 16);
        lp.x = (uint32_t)l[0] | ((uint32_t)l[1] << 16);
        lp.y = (uint32_t)l[2] | ((uint32_t)l[3] << 16);
        *dh = hp;
        *dl = lp;
    }
}

// ---------------------------------------------------------------------------
// Kernel 1: fp16-split HMMA GEMM.  logits = A * W^T + b  (M=16384,N=640,K=1024)
// CTA 128x64, BK=64 halves, 2-stage cp.async double buffer (2 CTAs/SM).
// 8 warps as 4(M) x 2(N); warp tile 32x32; acc0 = hi*hi, acc1 = cross terms.
// ---------------------------------------------------------------------------
__global__ __launch_bounds__(256, 2)
void gemm_hmma(const float* __restrict__ bias) {
    extern __shared__ char smem[];
    const uint32_t sb = smem_u32(smem);
    const int tid  = threadIdx.x;
    const int lane = tid & 31;
    const int wid  = tid >> 5;
    const int wm   = wid >> 1;   // 0..3 -> 32 rows each
    const int wn   = wid & 1;    // 0..1 -> 32 cols each
    const int m0 = blockIdx.y * MT;
    const int n0 = blockIdx.x * NTL;

    // per-lane ldmatrix row-byte offsets (within tile)
    const uint32_t ra = (uint32_t)(wm * 32 + (lane & 15)) * 128;
    const uint32_t ua = (uint32_t)(lane >> 4);            // A unit parity
    const uint32_t rb = (uint32_t)(wn * 32 + (lane & 7) + ((lane >> 4) << 3)) * 128;
    const uint32_t ub = (uint32_t)((lane >> 3) & 1);      // B unit parity

    auto load_stage = [&](int kc, int s) {
        const uint32_t base = sb + s * STG;
        const int k0 = kc * BKH;
#pragma unroll
        for (int i = 0; i < 4; i++) {
            const int q = tid + 256 * i;          // 0..1023
            const int r = q >> 3, u = q & 7;
            const uint32_t off = sw128((uint32_t)(r * 128 + u * 16));
            const size_t gs = (size_t)(m0 + r) * HID + k0 + u * 8;
            CPA16(base + off,        g_Ahi + gs);
            CPA16(base + A_SP + off, g_Alo + gs);
        }
#pragma unroll
        for (int i = 0; i < 2; i++) {
            const int q = tid + 256 * i;          // 0..511
            const int r = q >> 3, u = q & 7;      // r 0..63
            const uint32_t off = sw128((uint32_t)(r * 128 + u * 16));
            const size_t gs = (size_t)(n0 + r) * HID + k0 + u * 8;
            CPA16(base + 2 * A_SP + off,        g_Whi + gs);
            CPA16(base + 2 * A_SP + B_SP + off, g_Wlo + gs);
        }
    };

    float acc0[2][4][4], acc1[2][4][4];
#pragma unroll
    for (int mt = 0; mt < 2; mt++)
#pragma unroll
        for (int nt = 0; nt < 4; nt++)
#pragma unroll
            for (int e = 0; e < 4; e++) { acc0[mt][nt][e] = 0.f; acc1[mt][nt][e] = 0.f; }

    load_stage(0, 0); CP_COMMIT();

    for (int kc = 0; kc < NCHK; kc++) {
        if (kc + 1 < NCHK) {
            load_stage(kc + 1, (kc + 1) & 1);
            CP_COMMIT();
            CP_WAIT1();         // stage kc complete; kc+1 still in flight
        } else {
            CP_WAIT0();         // last stage
        }
        __syncthreads();        // stage kc visible to all warps

        const uint32_t base = sb + (kc & 1) * STG;
        const uint32_t aH = base, aL = base + A_SP;
        const uint32_t bH = base + 2 * A_SP, bL = bH + B_SP;

#pragma unroll
        for (int k16 = 0; k16 < 4; k16++) {
            const uint32_t ucA = (uint32_t)(k16 * 2 + ua) * 16;
            const uint32_t ucB = (uint32_t)(k16 * 2 + ub) * 16;
            uint32_t ah[2][4], al[2][4];
#pragma unroll
            for (int mt = 0; mt < 2; mt++) {
                const uint32_t off = sw128(ra + mt * 2048 + ucA);
                LDSM4(ah[mt][0], ah[mt][1], ah[mt][2], ah[mt][3], aH + off);
                LDSM4(al[mt][0], al[mt][1], al[mt][2], al[mt][3], aL + off);
            }
            uint32_t bh[8], bl[8];
#pragma unroll
            for (int nn = 0; nn < 2; nn++) {
                const uint32_t off = sw128(rb + nn * 2048 + ucB);
                LDSM4(bh[nn * 4 + 0], bh[nn * 4 + 1], bh[nn * 4 + 2], bh[nn * 4 + 3], bH + off);
                LDSM4(bl[nn * 4 + 0], bl[nn * 4 + 1], bl[nn * 4 + 2], bl[nn * 4 + 3], bL + off);
            }
#pragma unroll
            for (int mt = 0; mt < 2; mt++)
#pragma unroll
                for (int nt = 0; nt < 4; nt++) {
                    MMA16816(acc0[mt][nt], ah[mt], bh[nt * 2], bh[nt * 2 + 1]);
                    MMA16816(acc1[mt][nt], ah[mt], bl[nt * 2], bl[nt * 2 + 1]);
                    MMA16816(acc1[mt][nt], al[mt], bh[nt * 2], bh[nt * 2 + 1]);
                }
        }
        __syncthreads();        // all warps done with buffer (kc&1) before reload
    }

    // epilogue: logits = acc0 + acc1/4096 + bias
    const int mrow  = m0 + wm * 32 + (lane >> 2);
    const int ncol0 = n0 + wn * 32 + (lane & 3) * 2;
#pragma unroll
    for (int mt = 0; mt < 2; mt++)
#pragma unroll
        for (int nt = 0; nt < 4; nt++) {
            const int r = mrow + mt * 16;
            const int c = ncol0 + nt * 8;
            const float2 bv = *(const float2*)(bias + c);
            float2 o;
            o.x = acc0[mt][nt][0] + acc1[mt][nt][0] * (1.0f / 4096.0f) + bv.x;
            o.y = acc0[mt][nt][1] + acc1[mt][nt][1] * (1.0f / 4096.0f) + bv.y;
            *(float2*)(g_logits + (size_t)r * GV + c) = o;
            o.x = acc0[mt][nt][2] + acc1[mt][nt][2] * (1.0f / 4096.0f) + bv.x;
            o.y = acc0[mt][nt][3] + acc1[mt][nt][3] * (1.0f / 4096.0f) + bv.y;
            *(float2*)(g_logits + (size_t)(r + 8) * GV + c) = o;
        }
}

// ---------------------------------------------------------------------------
// Kernel 2: per-(n,g) row: gumbel argmax -> codevector gather + soft marginal
// ---------------------------------------------------------------------------
__global__ __launch_bounds__(256)
void rowreduce_kernel(const float* __restrict__ gumbel_u,
                      const float* __restrict__ codevec,
                      float* __restrict__ out) {
    const int g    = blockIdx.y;
    const int warp = threadIdx.x >> 5;
    const int lane = threadIdx.x & 31;
    __shared__ float marg[8][V];

    for (int v = lane; v < V; v += 32) marg[warp][v] = 0.f;

    const int nbase = blockIdx.x * ROWS_PER_BLK;
    for (int it = 0; it < ROWS_PER_BLK / 8; it++) {
        const int n = nbase + it * 8 + warp;
        const float* lrow = g_logits + (size_t)n * GV + g * V;
        const float* urow = gumbel_u + ((size_t)n * G + g) * V;

        float l[10];
        float key_max = -INFINITY; int key_idx = 0;
        float l_max   = -INFINITY;
#pragma unroll
        for (int s = 0; s < 10; s++) {
            const int v = lane + 32 * s;
            l[s] = lrow[v];
            const float u   = urow[v];
            const float gum = -logf(-logf(u));
            const float key = l[s] + gum;
            if (key > key_max) { key_max = key; key_idx = v; }
            l_max = fmaxf(l_max, l[s]);
        }
#pragma unroll
        for (int off = 16; off; off >>= 1)
            l_max = fmaxf(l_max, __shfl_xor_sync(0xffffffffu, l_max, off));
#pragma unroll
        for (int off = 16; off; off >>= 1) {
            const float ok = __shfl_xor_sync(0xffffffffu, key_max, off);
            const int   oi = __shfl_xor_sync(0xffffffffu, key_idx, off);
            if (ok > key_max || (ok == key_max && oi < key_idx)) {
                key_max = ok; key_idx = oi;
            }
        }
        float p[10];
        float sum = 0.f;
#pragma unroll
        for (int s = 0; s < 10; s++) { p[s] = expf(l[s] - l_max); sum += p[s]; }
#pragma unroll
        for (int off = 16; off; off >>= 1)
            sum += __shfl_xor_sync(0xffffffffu, sum, off);
        const float inv = 1.f / sum;
#pragma unroll
        for (int s = 0; s < 10; s++)
            marg[warp][lane + 32 * s] += p[s] * inv;

        const float4* src = (const float4*)(codevec + (size_t)(g * V + key_idx) * DHALF);
        float4* dst = (float4*)(out + (size_t)n * (2 * DHALF) + g * DHALF);
        dst[lane] = src[lane];
    }
    __syncthreads();

    for (int v = threadIdx.x; v < V; v += 256) {
        float s = 0.f;
#pragma unroll
        for (int w = 0; w < 8; w++) s += marg[w][v];
        g_part[(g * NBLK_B + blockIdx.x) * V + v] = s;
    }
}

// ---------------------------------------------------------------------------
// Kernel 3a: per-(g,v) marginal reduce -> m*log(m+1e-7). One warp per (g,v).
// 20 blocks x 1024 threads = 640 warps.
// ---------------------------------------------------------------------------
__global__ __launch_bounds__(1024)
void finalize1_kernel() {
    const int pair = blockIdx.x * 32 + (threadIdx.x >> 5);   // 0..639
    const int lane = threadIdx.x & 31;
    const int gg = pair / V;
    const int vv = pair % V;
    float s = 0.f;
#pragma unroll
    for (int k = 0; k < NBLK_B / 32; k++)
        s += g_part[(gg * NBLK_B + (lane + 32 * k)) * V + vv];
#pragma unroll
    for (int off = 16; off; off >>= 1)
        s += __shfl_xor_sync(0xffffffffu, s, off);
    if (lane == 0) {
        const float m = s / (float)NTOK;
        g_terms[pair] = m * logf(m + 1e-7f);
    }
}

// ---------------------------------------------------------------------------
// Kernel 3b: sum terms per group, ppl = exp(-H0)+exp(-H1). One warp.
// ---------------------------------------------------------------------------
__global__ void finalize2_kernel(float* __restrict__ out, int out_size) {
    const int lane = threadIdx.x;
    float h0 = 0.f, h1 = 0.f;
#pragma unroll
    for (int k = 0; k < V / 32; k++) {
        h0 += g_terms[lane + 32 * k];
        h1 += g_terms[V + lane + 32 * k];
    }
#pragma unroll
    for (int off = 16; off; off >>= 1) {
        h0 += __shfl_xor_sync(0xffffffffu, h0, off);
        h1 += __shfl_xor_sync(0xffffffffu, h1, off);
    }
    if (lane == 0 && out_size > NTOK * 2 * DHALF)
        out[(size_t)NTOK * 2 * DHALF] = expf(-h0) + expf(-h1);
}

// ---------------------------------------------------------------------------
extern "C" void kernel_launch(void* const* d_in, const int* in_sizes, int n_in,
                              void* d_out, int out_size) {
    const float* hidden      = (const float*)d_in[0];
    const float* W           = (const float*)d_in[1];
    const float* b           = (const float*)d_in[2];
    const float* codevectors = (const float*)d_in[3];
    const float* gumbel_u    = (const float*)d_in[4];
    float* out = (float*)d_out;

    cudaFuncSetAttribute(gemm_hmma, cudaFuncAttributeMaxDynamicSharedMemorySize, SMEM_GEMM);

    split_kernel<<<1024, 256>>>(hidden, W);

    dim3 ggrid(GV / NTL, NTOK / MT);    // (10, 128)
    gemm_hmma<<<ggrid, 256, SMEM_GEMM>>>(b);

    dim3 bgrid(NBLK_B, G);              // (256, 2)
    rowreduce_kernel<<<bgrid, 256>>>(gumbel_u, codevectors, out);

    finalize1_kernel<<<20, 1024>>>();
    finalize2_kernel<<<1, 32>>>(out, out_size);
}